// round 4
// baseline (speedup 1.0000x reference)
#include <cuda_runtime.h>
#include <cstdint>
#include <cstdio>

// Problem constants
namespace {
constexpr int Bb = 4, Tt = 4096, Cc = 2048, Hh = 16, DhD = 128;
constexpr int Mrows = Bb * Tt;            // 16384
constexpr int NCHUNK = 64;                // scan chunks
constexpr int LCH = Tt / NCHUNK;          // 64 steps per chunk
constexpr int BKk = 16;                   // k-floats per stage
constexpr int KCH = Cc / BKk;             // 128 stages
constexpr int NST = 4;                    // pipeline stages
constexpr int STW = 128 * BKk;            // 2048 words per (matrix,stage)
// dynamic smem: As(4 stages) + Bs(4 stages) + red[128*4]
constexpr int GEMM_SMEM = (2 * NST * STW) * 4 + 128 * 4 * 4;   // 67584 B
}

// ---------------- scratch (static device globals; no allocation allowed) ---
__device__ float g_xconv[(size_t)Bb * Tt * Cc];
__device__ float g_q   [(size_t)Bb * Tt * Cc];
__device__ float g_k   [(size_t)Bb * Tt * Cc];
__device__ float g_v   [(size_t)Bb * Tt * Cc];
__device__ float g_gate[(size_t)Bb * Tt * Cc];
__device__ float g_att [(size_t)Bb * Tt * Cc];
__device__ float g_y   [(size_t)Bb * Tt * Cc];
__device__ float g_xt  [(size_t)Bb * Tt * Cc];      // tf32-rounded x
__device__ float g_Wqt [(size_t)Cc * Cc];
__device__ float g_Wkt [(size_t)Cc * Cc];
__device__ float g_Wvt [(size_t)Cc * Cc];
__device__ float g_Wot [(size_t)Cc * Cc];
__device__ float g_Wgt [(size_t)Cc * Cc];
__device__ float g_F    [(size_t)Bb * Hh * NCHUNK * DhD];
__device__ float g_carry[(size_t)Bb * Hh * NCHUNK * DhD];

// ---------------- helpers --------------------------------------------------
__device__ __forceinline__ uint32_t f2tf32(float f) {
    uint32_t u;
    asm("cvt.rna.tf32.f32 %0, %1;" : "=r"(u) : "f"(f));
    return u;
}
__device__ __forceinline__ float tf32r(float f) { return __uint_as_float(f2tf32(f)); }

__device__ __forceinline__ void mma_tf32(float& d0, float& d1, float& d2, float& d3,
                                         uint32_t a0, uint32_t a1, uint32_t a2, uint32_t a3,
                                         uint32_t b0, uint32_t b1) {
    asm volatile(
        "mma.sync.aligned.m16n8k8.row.col.f32.tf32.tf32.f32 "
        "{%0,%1,%2,%3}, {%4,%5,%6,%7}, {%8,%9}, {%0,%1,%2,%3};\n"
        : "+f"(d0), "+f"(d1), "+f"(d2), "+f"(d3)
        : "r"(a0), "r"(a1), "r"(a2), "r"(a3), "r"(b0), "r"(b1));
}

#define LDMATRIX_X4(r0, r1, r2, r3, addr) \
    asm volatile("ldmatrix.sync.aligned.m8n8.x4.shared.b16 {%0,%1,%2,%3}, [%4];" \
                 : "=r"(r0), "=r"(r1), "=r"(r2), "=r"(r3) : "r"(addr))

// ---------------- 0) tf32 pre-round (vectorized) ----------------------------
__global__ void cvt_tf32_kernel(const float* __restrict__ in, float* __restrict__ out) {
    int i = blockIdx.x * blockDim.x + threadIdx.x;
    float4 v = reinterpret_cast<const float4*>(in)[i];
    v.x = tf32r(v.x); v.y = tf32r(v.y); v.z = tf32r(v.z); v.w = tf32r(v.w);
    reinterpret_cast<float4*>(out)[i] = v;
}

// ---------------- 1) causal depthwise conv (K=4) + SiLU (tf32-rounded out) --
__global__ void conv_silu_kernel(const float* __restrict__ x,
                                 const float* __restrict__ w,
                                 const float* __restrict__ bias) {
    int idx = blockIdx.x * blockDim.x + threadIdx.x;
    int c  = idx & (Cc - 1);
    int bt = idx >> 11;
    int t  = bt & (Tt - 1);
    float acc = bias[c];
    const float* wr = w + c * 4;
    int base = (bt - t) * Cc + c;
    #pragma unroll
    for (int j = 0; j < 4; j++) {
        int tt = t - 3 + j;
        if (tt >= 0) acc = fmaf(x[base + tt * Cc], wr[j], acc);
    }
    float s = acc / (1.0f + expf(-acc));
    g_xconv[idx] = tf32r(s);
}

// ---------------- 2) TF32 mma.sync GEMM, 4-stage cp.async, ldmatrix ---------
// Out = A[M,K] * W[N,K]^T.  A, W pre-rounded to tf32.
// mode 0: plain.  mode 1: sigmoid(out+bias[col]).  mode 2: per-row l2norm
// over the 128-col tile (tile == one head since BN=128).
__global__ __launch_bounds__(256, 1)
void gemm_tf32_lm(const float* __restrict__ A, const float* __restrict__ W,
                  float* __restrict__ Out, const float* __restrict__ bias, int mode) {
    extern __shared__ uint32_t dyn[];
    uint32_t* AsB = dyn;                 // NST * STW words
    uint32_t* BsB = dyn + NST * STW;     // NST * STW words
    float*    red = (float*)(dyn + 2 * NST * STW);   // 128*4 floats

    const int tid  = threadIdx.x;
    const int warp = tid >> 5, lane = tid & 31;
    const int gid  = lane >> 2, tg = lane & 3;
    const int wm   = warp & 1;
    const int wn   = warp >> 1;
    const int bm   = blockIdx.y * 128;
    const int bn   = blockIdx.x * 128;

    const int lr = tid >> 2;             // 0..63 loader row
    const int lc = tid & 3;              // 16B chunk 0..3

    const uint32_t sA = (uint32_t)__cvta_generic_to_shared(AsB);
    const uint32_t sB = (uint32_t)__cvta_generic_to_shared(BsB);

    auto issue = [&](int s, int k0) {
        #pragma unroll
        for (int r = 0; r < 2; r++) {
            int row = lr + r * 64;
            int sw  = (row >> 1) & 3;
            uint32_t off = (uint32_t)(s * STW + row * 16 + ((lc ^ sw) << 2)) * 4u;
            const float* gA = A + (size_t)(bm + row) * Cc + k0 + lc * 4;
            asm volatile("cp.async.cg.shared.global [%0], [%1], 16;\n" :: "r"(sA + off), "l"(gA));
            const float* gB = W + (size_t)(bn + row) * Cc + k0 + lc * 4;
            asm volatile("cp.async.cg.shared.global [%0], [%1], 16;\n" :: "r"(sB + off), "l"(gB));
        }
        asm volatile("cp.async.commit_group;\n" ::: "memory");
    };

    // ldmatrix lane constants (swizzle-invariant derivations; see analysis)
    const uint32_t hiA     = lane >> 4;                  // 0/1: col-chunk select
    const uint32_t swA     = ((lane & 15) >> 1) & 3;
    const uint32_t rowAoff = (uint32_t)((wm * 64 + (lane & 15)) * 16);
    const uint32_t hiB     = (lane >> 3) & 1;
    const uint32_t swB     = ((lane & 7) >> 1) & 3;
    const uint32_t rowBoff = (uint32_t)((wn * 32 + ((lane >> 4) << 3) + (lane & 7)) * 16);

    float acc[4][4][4] = {};

    issue(0, 0);
    issue(1, BKk);
    issue(2, 2 * BKk);

    for (int i = 0; i < KCH; i++) {
        const int s = i & 3;
        if (i < KCH - 2)       asm volatile("cp.async.wait_group 2;\n" ::: "memory");
        else if (i == KCH - 2) asm volatile("cp.async.wait_group 1;\n" ::: "memory");
        else                   asm volatile("cp.async.wait_group 0;\n" ::: "memory");
        __syncthreads();

        if (i + 3 < KCH) issue((i + 3) & 3, (i + 3) * BKk);

        const uint32_t aS = sA + (uint32_t)(s * STW) * 4u;
        const uint32_t bS = sB + (uint32_t)(s * STW) * 4u;

        #pragma unroll
        for (int half = 0; half < 2; half++) {
            const uint32_t c0 = half * 2;
            uint32_t af[4][4];
            #pragma unroll
            for (int mt = 0; mt < 4; mt++) {
                uint32_t addr = aS + ((rowAoff + mt * 256 + ((((c0 + hiA) ^ swA)) << 2)) << 2);
                LDMATRIX_X4(af[mt][0], af[mt][1], af[mt][2], af[mt][3], addr);
            }
            uint32_t bf[4][2];
            #pragma unroll
            for (int ntp = 0; ntp < 2; ntp++) {
                uint32_t addr = bS + ((rowBoff + ntp * 256 + ((((c0 + hiB) ^ swB)) << 2)) << 2);
                LDMATRIX_X4(bf[2 * ntp][0], bf[2 * ntp][1],
                            bf[2 * ntp + 1][0], bf[2 * ntp + 1][1], addr);
            }
            #pragma unroll
            for (int mt = 0; mt < 4; mt++)
                #pragma unroll
                for (int nt = 0; nt < 4; nt++)
                    mma_tf32(acc[mt][nt][0], acc[mt][nt][1], acc[mt][nt][2], acc[mt][nt][3],
                             af[mt][0], af[mt][1], af[mt][2], af[mt][3],
                             bf[nt][0], bf[nt][1]);
        }
    }
    __syncthreads();

    // ---- fused l2norm over the 128-col tile (mode 2) ------------------------
    float invLo[4], invHi[4];
    if (mode == 2) {
        #pragma unroll
        for (int mt = 0; mt < 4; mt++) {
            float slo = 0.0f, shi = 0.0f;
            #pragma unroll
            for (int nt = 0; nt < 4; nt++) {
                slo = fmaf(acc[mt][nt][0], acc[mt][nt][0], slo);
                slo = fmaf(acc[mt][nt][1], acc[mt][nt][1], slo);
                shi = fmaf(acc[mt][nt][2], acc[mt][nt][2], shi);
                shi = fmaf(acc[mt][nt][3], acc[mt][nt][3], shi);
            }
            slo += __shfl_xor_sync(0xffffffffu, slo, 1);
            slo += __shfl_xor_sync(0xffffffffu, slo, 2);
            shi += __shfl_xor_sync(0xffffffffu, shi, 1);
            shi += __shfl_xor_sync(0xffffffffu, shi, 2);
            if (tg == 0) {
                int r = wm * 64 + mt * 16 + gid;
                red[r * 4 + wn]       = slo;
                red[(r + 8) * 4 + wn] = shi;
            }
        }
        __syncthreads();
        #pragma unroll
        for (int mt = 0; mt < 4; mt++) {
            int r = wm * 64 + mt * 16 + gid;
            float slo = red[r * 4 + 0] + red[r * 4 + 1] + red[r * 4 + 2] + red[r * 4 + 3];
            float shi = red[(r + 8) * 4 + 0] + red[(r + 8) * 4 + 1]
                      + red[(r + 8) * 4 + 2] + red[(r + 8) * 4 + 3];
            invLo[mt] = 1.0f / fmaxf(sqrtf(slo), 1e-12f);
            invHi[mt] = 1.0f / fmaxf(sqrtf(shi), 1e-12f);
        }
        #pragma unroll
        for (int mt = 0; mt < 4; mt++)
            #pragma unroll
            for (int nt = 0; nt < 4; nt++) {
                acc[mt][nt][0] *= invLo[mt];
                acc[mt][nt][1] *= invLo[mt];
                acc[mt][nt][2] *= invHi[mt];
                acc[mt][nt][3] *= invHi[mt];
            }
    }

    // ---- stores --------------------------------------------------------------
    #pragma unroll
    for (int mt = 0; mt < 4; mt++) {
        #pragma unroll
        for (int nt = 0; nt < 4; nt++) {
            int row = bm + wm * 64 + mt * 16 + gid;
            int col = bn + wn * 32 + nt * 8 + tg * 2;
            float v0 = acc[mt][nt][0], v1 = acc[mt][nt][1];
            float v2 = acc[mt][nt][2], v3 = acc[mt][nt][3];
            if (mode == 1) {
                float b0 = bias[col], b1 = bias[col + 1];
                v0 = 1.0f / (1.0f + expf(-(v0 + b0)));
                v1 = 1.0f / (1.0f + expf(-(v1 + b1)));
                v2 = 1.0f / (1.0f + expf(-(v2 + b0)));
                v3 = 1.0f / (1.0f + expf(-(v3 + b1)));
            }
            *reinterpret_cast<float2*>(&Out[(size_t)row * Cc + col])       = make_float2(v0, v1);
            *reinterpret_cast<float2*>(&Out[(size_t)(row + 8) * Cc + col]) = make_float2(v2, v3);
        }
    }
}

// ---------------- 4) chunked decayed scan ----------------------------------
__global__ void scan_pass1(const float* __restrict__ k, const float* __restrict__ v,
                           const float* __restrict__ gamma) {
    int blk = blockIdx.x;
    int c  = blk % NCHUNK;
    int bh = blk / NCHUNK;
    int h  = bh % Hh;
    int b  = bh / Hh;
    int d  = threadIdx.x;
    float g = gamma[h];
    size_t idx = ((size_t)(b * Tt + c * LCH)) * Cc + h * DhD + d;
    float S = 0.0f;
    #pragma unroll 4
    for (int i = 0; i < LCH; i++) {
        S = fmaf(g, S, k[idx] * v[idx]);
        idx += Cc;
    }
    g_F[((size_t)bh * NCHUNK + c) * DhD + d] = S;
}

__global__ void scan_pass2(const float* __restrict__ gamma) {
    int tid = blockIdx.x * blockDim.x + threadIdx.x;
    if (tid >= Bb * Hh * DhD) return;
    int d  = tid & (DhD - 1);
    int bh = tid >> 7;
    int h  = bh % Hh;
    float g  = gamma[h];
    float gL = powf(g, (float)LCH);
    float carry = 0.0f;
    for (int c = 0; c < NCHUNK; c++) {
        size_t o = ((size_t)bh * NCHUNK + c) * DhD + d;
        g_carry[o] = carry;
        carry = fmaf(gL, carry, g_F[o]);
    }
}

__global__ void scan_pass3(const float* __restrict__ k, const float* __restrict__ v,
                           const float* __restrict__ q, const float* __restrict__ gate,
                           const float* __restrict__ gamma) {
    int blk = blockIdx.x;
    int c  = blk % NCHUNK;
    int bh = blk / NCHUNK;
    int h  = bh % Hh;
    int b  = bh / Hh;
    int d  = threadIdx.x;
    float g = gamma[h];
    float S = g_carry[((size_t)bh * NCHUNK + c) * DhD + d];
    size_t idx = ((size_t)(b * Tt + c * LCH)) * Cc + h * DhD + d;
    #pragma unroll 4
    for (int i = 0; i < LCH; i++) {
        S = fmaf(g, S, k[idx] * v[idx]);
        g_att[idx] = tf32r(gate[idx] * S * q[idx]);
        idx += Cc;
    }
}

// ---------------- 5) LayerNorm over C=2048 ---------------------------------
__global__ __launch_bounds__(256)
void ln_kernel(const float* __restrict__ y, const float* __restrict__ lw,
               const float* __restrict__ lb, float* __restrict__ out) {
    int row = blockIdx.x;
    int tid = threadIdx.x;
    const float4* yr = reinterpret_cast<const float4*>(y + (size_t)row * Cc);
    float4* orow     = reinterpret_cast<float4*>(out + (size_t)row * Cc);

    float4 v0 = yr[tid];
    float4 v1 = yr[tid + 256];
    float sum = v0.x + v0.y + v0.z + v0.w + v1.x + v1.y + v1.z + v1.w;
    float sq  = v0.x * v0.x + v0.y * v0.y + v0.z * v0.z + v0.w * v0.w
              + v1.x * v1.x + v1.y * v1.y + v1.z * v1.z + v1.w * v1.w;

    #pragma unroll
    for (int o = 16; o; o >>= 1) {
        sum += __shfl_xor_sync(0xffffffffu, sum, o);
        sq  += __shfl_xor_sync(0xffffffffu, sq, o);
    }
    __shared__ float ssum[8], ssq[8];
    __shared__ float s_mu, s_inv;
    int warp = tid >> 5, lane = tid & 31;
    if (lane == 0) { ssum[warp] = sum; ssq[warp] = sq; }
    __syncthreads();
    if (tid == 0) {
        float ts = 0.0f, tq = 0.0f;
        #pragma unroll
        for (int i = 0; i < 8; i++) { ts += ssum[i]; tq += ssq[i]; }
        float mu  = ts / (float)Cc;
        float var = tq / (float)Cc - mu * mu;
        s_mu  = mu;
        s_inv = rsqrtf(var + 1e-5f);
    }
    __syncthreads();
    float mu = s_mu, inv = s_inv;

    const float4 w0 = reinterpret_cast<const float4*>(lw)[tid];
    const float4 w1 = reinterpret_cast<const float4*>(lw)[tid + 256];
    const float4 b0 = reinterpret_cast<const float4*>(lb)[tid];
    const float4 b1 = reinterpret_cast<const float4*>(lb)[tid + 256];

    float4 o0, o1;
    o0.x = (v0.x - mu) * inv * w0.x + b0.x;
    o0.y = (v0.y - mu) * inv * w0.y + b0.y;
    o0.z = (v0.z - mu) * inv * w0.z + b0.z;
    o0.w = (v0.w - mu) * inv * w0.w + b0.w;
    o1.x = (v1.x - mu) * inv * w1.x + b1.x;
    o1.y = (v1.y - mu) * inv * w1.y + b1.y;
    o1.z = (v1.z - mu) * inv * w1.z + b1.z;
    o1.w = (v1.w - mu) * inv * w1.w + b1.w;
    orow[tid]       = o0;
    orow[tid + 256] = o1;
}

// ---------------- host orchestration ---------------------------------------
extern "C" void kernel_launch(void* const* d_in, const int* in_sizes, int n_in,
                              void* d_out, int out_size) {
    (void)in_sizes; (void)n_in; (void)out_size;
    const float* x      = (const float*)d_in[0];
    const float* Wq     = (const float*)d_in[1];
    const float* Wk     = (const float*)d_in[2];
    const float* Wv     = (const float*)d_in[3];
    const float* Wo     = (const float*)d_in[4];
    const float* conv_w = (const float*)d_in[5];
    const float* conv_b = (const float*)d_in[6];
    const float* gate_w = (const float*)d_in[7];
    const float* gate_b = (const float*)d_in[8];
    const float* ln_w   = (const float*)d_in[9];
    const float* ln_b   = (const float*)d_in[10];
    const float* gamma  = (const float*)d_in[11];

    float *p_xconv, *p_q, *p_k, *p_v, *p_gate, *p_att, *p_y;
    float *p_xt, *p_Wqt, *p_Wkt, *p_Wvt, *p_Wot, *p_Wgt;
    cudaGetSymbolAddress((void**)&p_xconv, g_xconv);
    cudaGetSymbolAddress((void**)&p_q, g_q);
    cudaGetSymbolAddress((void**)&p_k, g_k);
    cudaGetSymbolAddress((void**)&p_v, g_v);
    cudaGetSymbolAddress((void**)&p_gate, g_gate);
    cudaGetSymbolAddress((void**)&p_att, g_att);
    cudaGetSymbolAddress((void**)&p_y, g_y);
    cudaGetSymbolAddress((void**)&p_xt, g_xt);
    cudaGetSymbolAddress((void**)&p_Wqt, g_Wqt);
    cudaGetSymbolAddress((void**)&p_Wkt, g_Wkt);
    cudaGetSymbolAddress((void**)&p_Wvt, g_Wvt);
    cudaGetSymbolAddress((void**)&p_Wot, g_Wot);
    cudaGetSymbolAddress((void**)&p_Wgt, g_Wgt);

    cudaFuncSetAttribute(gemm_tf32_lm, cudaFuncAttributeMaxDynamicSharedMemorySize, GEMM_SMEM);

    // 0) pre-round GEMM operands to tf32
    const int wElems = Cc * Cc;
    cvt_tf32_kernel<<<wElems / 1024, 256>>>(Wq, p_Wqt);
    cvt_tf32_kernel<<<wElems / 1024, 256>>>(Wk, p_Wkt);
    cvt_tf32_kernel<<<wElems / 1024, 256>>>(Wv, p_Wvt);
    cvt_tf32_kernel<<<wElems / 1024, 256>>>(Wo, p_Wot);
    cvt_tf32_kernel<<<wElems / 1024, 256>>>(gate_w, p_Wgt);
    cvt_tf32_kernel<<<(Mrows * Cc) / 1024, 256>>>(x, p_xt);

    // 1) depthwise conv + SiLU
    conv_silu_kernel<<<(Mrows * Cc) / 256, 256>>>(x, conv_w, conv_b);

    // 2) projections.  mode: 0 plain, 1 sigmoid+bias, 2 fused l2norm (1 head/tile)
    dim3 ggrid(Cc / 128, Mrows / 128);   // (16, 128)
    gemm_tf32_lm<<<ggrid, 256, GEMM_SMEM>>>(p_xt,    p_Wqt, p_q,    nullptr, 2);
    gemm_tf32_lm<<<ggrid, 256, GEMM_SMEM>>>(p_xt,    p_Wkt, p_k,    nullptr, 2);
    gemm_tf32_lm<<<ggrid, 256, GEMM_SMEM>>>(p_xt,    p_Wvt, p_v,    nullptr, 0);
    gemm_tf32_lm<<<ggrid, 256, GEMM_SMEM>>>(p_xconv, p_Wgt, p_gate, gate_b, 1);

    // 3) decayed scan (chunked, exact); q/k already l2-normalized in epilogue
    scan_pass1<<<Bb * Hh * NCHUNK, DhD>>>(p_k, p_v, gamma);
    scan_pass2<<<(Bb * Hh * DhD + 127) / 128, 128>>>(gamma);
    scan_pass3<<<Bb * Hh * NCHUNK, DhD>>>(p_k, p_v, p_q, p_gate, gamma);

    // 4) output projection + LayerNorm
    gemm_tf32_lm<<<ggrid, 256, GEMM_SMEM>>>(p_att, p_Wot, p_y, nullptr, 0);
    ln_kernel<<<Mrows, 256>>>(p_y, ln_w, ln_b, (float*)d_out);
}